// round 17
// baseline (speedup 1.0000x reference)
#include <cuda_runtime.h>
#include <cuda_bf16.h>
#include <cstdint>

#define SEQ 2048
#define HD  64
#define OUT_ELEMS (16*SEQ*HD)
#define KV_ELEMS (16*SEQ*HD)   // 2M elements

__device__ float g_rowsum[16 * SEQ];
__device__ __nv_bfloat16 g_kh[KV_ELEMS];
__device__ __nv_bfloat16 g_kl[KV_ELEMS];
__device__ __nv_bfloat16 g_vh[KV_ELEMS];
__device__ __nv_bfloat16 g_vl[KV_ELEMS];

// ---------------- helpers ----------------
__device__ __forceinline__ uint32_t smem_u32(const void* p) {
    uint32_t a;
    asm("{ .reg .u64 t; cvta.to.shared.u64 t, %1; cvt.u32.u64 %0, t; }" : "=r"(a) : "l"(p));
    return a;
}

#define CP16(dst, src) \
    asm volatile("cp.async.cg.shared.global [%0], [%1], 16;" :: "r"(dst), "l"(src))
#define CP_COMMIT() asm volatile("cp.async.commit_group;" ::: "memory")
#define CP_WAIT(n)  asm volatile("cp.async.wait_group %0;" :: "n"(n) : "memory")

#define LDSM4(r, a) \
    asm volatile("ldmatrix.sync.aligned.m8n8.x4.shared.b16 {%0,%1,%2,%3}, [%4];" \
        : "=r"((r)[0]), "=r"((r)[1]), "=r"((r)[2]), "=r"((r)[3]) : "r"(a))
#define LDSM2(r, a) \
    asm volatile("ldmatrix.sync.aligned.m8n8.x2.shared.b16 {%0,%1}, [%2];" \
        : "=r"((r)[0]), "=r"((r)[1]) : "r"(a))
#define LDSM4T(r, a) \
    asm volatile("ldmatrix.sync.aligned.m8n8.x4.trans.shared.b16 {%0,%1,%2,%3}, [%4];" \
        : "=r"((r)[0]), "=r"((r)[1]), "=r"((r)[2]), "=r"((r)[3]) : "r"(a))

__device__ __forceinline__ void mma16816(float* d, const uint32_t* a, const uint32_t* b) {
    asm volatile(
        "mma.sync.aligned.m16n8k16.row.col.f32.bf16.bf16.f32 "
        "{%0,%1,%2,%3}, {%4,%5,%6,%7}, {%8,%9}, {%0,%1,%2,%3};"
        : "+f"(d[0]), "+f"(d[1]), "+f"(d[2]), "+f"(d[3])
        : "r"(a[0]), "r"(a[1]), "r"(a[2]), "r"(a[3]), "r"(b[0]), "r"(b[1]));
}

// fast 2^t : FFMA-only. |t| < 60 assumed.
__device__ __forceinline__ float fexp2(float t) {
    float z = t + 12582912.0f;
    int   i = __float_as_int(z);
    float f = t - (z - 12582912.0f);
    float p =          1.33335581e-3f;
    p = fmaf(p, f, 9.61812910e-3f);
    p = fmaf(p, f, 5.55041087e-2f);
    p = fmaf(p, f, 2.40226507e-1f);
    p = fmaf(p, f, 6.93147180e-1f);
    p = fmaf(p, f, 1.0f);
    float sc = __int_as_float((i + 127) << 23);
    return p * sc;
}
#define EXSCL 0.18033688011f   // 0.125 * log2(e)

// bf16 tiles: 64 elems (128B) per row, 16B-chunk xor swizzle
#define SW(o) ((o) ^ (((o) >> 3) & 0x70))
__device__ __forceinline__ uint32_t swz(uint32_t base, int row, int chunk) {
    return base + row * 128 + (((chunk ^ (row & 7)) & 7) << 4);
}

// split f32x4 -> bf16 hi/lo pairs
__device__ __forceinline__ void split_u2(float4 v, uint2& hp, uint2& lp) {
    __nv_bfloat162 h0 = __floats2bfloat162_rn(v.x, v.y);
    __nv_bfloat162 h1 = __floats2bfloat162_rn(v.z, v.w);
    float2 f0 = __bfloat1622float2(h0), f1 = __bfloat1622float2(h1);
    __nv_bfloat162 l0 = __floats2bfloat162_rn(v.x - f0.x, v.y - f0.y);
    __nv_bfloat162 l1 = __floats2bfloat162_rn(v.z - f1.x, v.w - f1.y);
    hp = make_uint2(reinterpret_cast<uint32_t&>(h0), reinterpret_cast<uint32_t&>(h1));
    lp = make_uint2(reinterpret_cast<uint32_t&>(l0), reinterpret_cast<uint32_t&>(l1));
}
__device__ __forceinline__ void store_split4(float4 v, char* hb, char* lb, int off) {
    uint2 hp, lp;
    split_u2(v, hp, lp);
    int s0 = SW(off);
    *(uint2*)(hb + s0) = hp;
    *(uint2*)(lb + s0) = lp;
}

// ---------------- prep: split K,V into global bf16 hi/lo planes --------------
__global__ void __launch_bounds__(256) split_kv(
    const float* __restrict__ K, const float* __restrict__ V)
{
    const int i = blockIdx.x * 256 + threadIdx.x;     // float4 index, 524288 total
    float4 k4 = ((const float4*)K)[i];
    float4 v4 = ((const float4*)V)[i];
    uint2 hp, lp;
    split_u2(k4, hp, lp);
    *(uint2*)(g_kh + (size_t)i * 4) = hp;
    *(uint2*)(g_kl + (size_t)i * 4) = lp;
    split_u2(v4, hp, lp);
    *(uint2*)(g_vh + (size_t)i * 4) = hp;
    *(uint2*)(g_vl + (size_t)i * 4) = lp;
}

// ------------------- Kernel A: S=QK^T, exp epilogue, rowsum -------------------
// 64-row q-tiles x 64-wide k-tiles. K hi/lo planes staged via cp.async,
// 4-stage pipeline; m/p register prefetch; direct fragment epilogue.
// smem: QH 8K | QL 8K | K stages 4x16K | rs
#define S_QH 0
#define S_QL 8192
#define S_ST(s) (16384 + (s)*16384)
#define S_RS (16384 + 4*16384)
#define S_SZ (S_RS + 768)

__global__ void __launch_bounds__(256, 2) scores_k(
    const float* __restrict__ Q,
    const int* __restrict__ Mk, const float* __restrict__ P, float* __restrict__ E)
{
    extern __shared__ char sm[];
    const uint32_t sb = smem_u32(sm);
    const int t = threadIdx.x, w = t >> 5, lane = t & 31;
    const int mw = w >> 1, nw = w & 1;     // warp tile: rows mw*16, cols nw*32
    const int bh = blockIdx.y, q0 = blockIdx.x * 64;

    const float* Qb = Q + ((size_t)bh * SEQ + q0) * HD;
    const size_t kbase = (size_t)bh * SEQ * HD;

    // issue K stage copies for tile kt into stage s
    const int cr0 = t >> 3, cc0 = t & 7;   // 256 threads -> 2 chunks/plane
    auto issue_k = [&](int s, int kt) {
        const uint32_t stg = sb + S_ST(s);
#pragma unroll
        for (int i = 0; i < 2; i++) {
            int row = cr0 + i * 32, ch = cc0;
            size_t gi = kbase + (size_t)(kt * 64 + row) * HD + ch * 8;
            CP16(swz(stg, row, ch), g_kh + gi);
            CP16(swz(stg + 8192, row, ch), g_kl + gi);
        }
    };

    // resident Q (64 x 64) split to smem
#pragma unroll
    for (int i = 0; i < 4; i++) {
        int idx = t + i * 256, r = idx >> 4, c = idx & 15;
        store_split4(*(const float4*)(Qb + r * HD + c * 4), sm + S_QH, sm + S_QL, r * 128 + c * 8);
    }

    // prologue: stages 0..2
    issue_k(0, 0); CP_COMMIT();
    issue_k(1, 1); CP_COMMIT();
    issue_k(2, 2); CP_COMMIT();

    float rs0 = 0.0f, rs1 = 0.0f;
    const int fr = lane >> 2;
    const int fc = 2 * (lane & 3);
    const size_t gr0 = ((size_t)(bh * SEQ + q0 + mw * 16 + fr)) * SEQ;
    const size_t gr1 = gr0 + 8 * SEQ;

    for (int kt = 0; kt < 32; kt++) {
        CP_WAIT(2);                 // stage kt ready
        __syncthreads();            // all warps done with stage (kt+3)&3 reads
        if (kt + 3 < 32) issue_k((kt + 3) & 3, kt + 3);
        CP_COMMIT();                // uniform group count (empty ok)

        // prefetch mask/p for THIS tile (consumed after MMA; latency hidden)
        const size_t cb = (size_t)kt * 64 + nw * 32 + fc;
        int2   m0[4], m1[4];
        float2 pp0[4], pp1[4];
#pragma unroll
        for (int ni = 0; ni < 4; ni++) {
            size_t g0 = gr0 + cb + ni * 8;
            m0[ni]  = *(const int2*)  (Mk + g0);
            pp0[ni] = *(const float2*)(P + g0);
            size_t g1 = gr1 + cb + ni * 8;
            m1[ni]  = *(const int2*)  (Mk + g1);
            pp1[ni] = *(const float2*)(P + g1);
        }

        // ---- S = Q K^T for this 64-k tile ----
        const uint32_t khs = sb + S_ST(kt & 3), kls = khs + 8192;
        float acc[4][4];
#pragma unroll
        for (int ni = 0; ni < 4; ni++)
#pragma unroll
            for (int j = 0; j < 4; j++) acc[ni][j] = 0.0f;

#pragma unroll
        for (int kc = 0; kc < 4; kc++) {
            uint32_t ah[4], al[4];
            LDSM4(ah, swz(sb + S_QH, mw * 16 + (lane & 15), kc * 2 + (lane >> 4)));
            LDSM4(al, swz(sb + S_QL, mw * 16 + (lane & 15), kc * 2 + (lane >> 4)));
#pragma unroll
            for (int ni = 0; ni < 4; ni++) {
                uint32_t bh2[2], bl2[2];
                const int nb = nw * 32 + ni * 8 + (lane & 7);
                LDSM2(bh2, swz(khs, nb, kc * 2 + ((lane >> 3) & 1)));
                LDSM2(bl2, swz(kls, nb, kc * 2 + ((lane >> 3) & 1)));
                mma16816(acc[ni], ah, bh2);
                mma16816(acc[ni], ah, bl2);
                mma16816(acc[ni], al, bh2);
            }
        }

        // ---- epilogue: pure register compute + stores ----
#pragma unroll
        for (int ni = 0; ni < 4; ni++) {
            float2 e0;
            e0.x = m0[ni].x ? (pp0[ni].x + 1e-12f) * fexp2(acc[ni][0] * EXSCL) : 0.0f;
            e0.y = m0[ni].y ? (pp0[ni].y + 1e-12f) * fexp2(acc[ni][1] * EXSCL) : 0.0f;
            *(float2*)(E + gr0 + cb + ni * 8) = e0;
            rs0 += e0.x + e0.y;
            float2 e1;
            e1.x = m1[ni].x ? (pp1[ni].x + 1e-12f) * fexp2(acc[ni][2] * EXSCL) : 0.0f;
            e1.y = m1[ni].y ? (pp1[ni].y + 1e-12f) * fexp2(acc[ni][3] * EXSCL) : 0.0f;
            *(float2*)(E + gr1 + cb + ni * 8) = e1;
            rs1 += e1.x + e1.y;
        }
    }

    rs0 += __shfl_xor_sync(0xffffffffu, rs0, 1);
    rs0 += __shfl_xor_sync(0xffffffffu, rs0, 2);
    rs1 += __shfl_xor_sync(0xffffffffu, rs1, 1);
    rs1 += __shfl_xor_sync(0xffffffffu, rs1, 2);
    float* rss = (float*)(sm + S_RS);
    if ((lane & 3) == 0) {
        rss[nw * 64 + mw * 16 + fr]     = rs0;
        rss[nw * 64 + mw * 16 + fr + 8] = rs1;
    }
    __syncthreads();
    if (t < 64) g_rowsum[bh * SEQ + q0 + t] = rss[t] + rss[64 + t];
}

// --------------- Kernel B: normalize E in place + O = p_attn V ---------------
// E: register prefetch + split (f32 write-back needed). V: cp.async planes,
// 4-stage. smem: E stages 2x16K | V stages 4x16K | inv
#define B_EST(s) ((s)*16384)
#define B_VST(s) (32768 + (s)*16384)
#define B_IV (32768 + 4*16384)
#define B_SZ (B_IV + 256)

__global__ void __launch_bounds__(256, 2) pv_k(
    float* __restrict__ E, float* __restrict__ O)
{
    extern __shared__ char sm[];
    const uint32_t sb = smem_u32(sm);
    const int t = threadIdx.x, w = t >> 5, lane = t & 31;
    const int mw = w >> 1, nw = w & 1;
    const int bh = blockIdx.y, q0 = blockIdx.x * 64;

    const size_t vbase = (size_t)bh * SEQ * HD;
    const int cr0 = t >> 3, cc0 = t & 7;
    auto issue_v = [&](int s, int kt) {
        const uint32_t stg = sb + B_VST(s);
#pragma unroll
        for (int i = 0; i < 2; i++) {
            int row = cr0 + i * 32, ch = cc0;
            size_t gi = vbase + (size_t)(kt * 64 + row) * HD + ch * 8;
            CP16(swz(stg, row, ch), g_vh + gi);
            CP16(swz(stg + 8192, row, ch), g_vl + gi);
        }
    };

    float* sinv = (float*)(sm + B_IV);
    if (t < 64) sinv[t] = 1.0f / g_rowsum[bh * SEQ + q0 + t];

    float* Eb = E + ((size_t)bh * SEQ + q0) * SEQ;

    const int r_ = t >> 4, c_ = t & 15;

    float4 er[4];
#pragma unroll
    for (int i = 0; i < 4; i++)
        er[i] = *(const float4*)(Eb + (size_t)(r_ + i * 16) * SEQ + c_ * 4);

    issue_v(0, 0); CP_COMMIT();
    issue_v(1, 1); CP_COMMIT();
    issue_v(2, 2); CP_COMMIT();

    float acc[4][4];
#pragma unroll
    for (int ni = 0; ni < 4; ni++)
#pragma unroll
        for (int j = 0; j < 4; j++) acc[ni][j] = 0.0f;

    __syncthreads();   // sinv visible

    for (int kt = 0; kt < 32; kt++) {
        const int es = kt & 1;
        char* EH = sm + B_EST(es);
        char* EL = EH + 8192;
        // normalize prefetched E, write back, split to E smem stage
#pragma unroll
        for (int i = 0; i < 4; i++) {
            const int r = r_ + i * 16;
            const float inv = sinv[r];
            float4 v = er[i];
            v.x *= inv; v.y *= inv; v.z *= inv; v.w *= inv;
            *(float4*)(Eb + (size_t)r * SEQ + kt * 64 + c_ * 4) = v;
            store_split4(v, EH, EL, r * 128 + c_ * 8);
        }
        CP_WAIT(2);                 // V stage kt ready
        __syncthreads();            // E stage published; all done with V stage (kt+3)&3
        if (kt + 3 < 32) issue_v((kt + 3) & 3, kt + 3);
        CP_COMMIT();
        if (kt < 31) {
#pragma unroll
            for (int i = 0; i < 4; i++)
                er[i] = *(const float4*)(Eb + (size_t)(r_ + i * 16) * SEQ + (kt + 1) * 64 + c_ * 4);
        }
        const uint32_t ehs = sb + B_EST(es), els = ehs + 8192;
        const uint32_t vhs = sb + B_VST(kt & 3), vls = vhs + 8192;
        const int vchk_off = lane >> 4;
#pragma unroll
        for (int kc = 0; kc < 4; kc++) {
            uint32_t bhf[2][4], blf[2][4];
#pragma unroll
            for (int ni2 = 0; ni2 < 2; ni2++) {
                const int nch = nw * 4 + ni2 * 2 + vchk_off;
                LDSM4T(bhf[ni2], swz(vhs, kc * 16 + (lane & 15), nch));
                LDSM4T(blf[ni2], swz(vls, kc * 16 + (lane & 15), nch));
            }
            uint32_t ah[4], al[4];
            LDSM4(ah, swz(ehs, mw * 16 + (lane & 15), kc * 2 + (lane >> 4)));
            LDSM4(al, swz(els, mw * 16 + (lane & 15), kc * 2 + (lane >> 4)));
#pragma unroll
            for (int ni2 = 0; ni2 < 2; ni2++) {
                mma16816(acc[2 * ni2],     ah, bhf[ni2]);
                mma16816(acc[2 * ni2],     ah, blf[ni2]);
                mma16816(acc[2 * ni2],     al, bhf[ni2]);
                mma16816(acc[2 * ni2 + 1], ah, bhf[ni2] + 2);
                mma16816(acc[2 * ni2 + 1], ah, blf[ni2] + 2);
                mma16816(acc[2 * ni2 + 1], al, bhf[ni2] + 2);
            }
        }
    }

    const int r0 = mw * 16 + (lane >> 2);
    const int c0 = nw * 32 + 2 * (lane & 3);
#pragma unroll
    for (int ni = 0; ni < 4; ni++) {
        size_t g0 = ((size_t)(bh * SEQ + q0 + r0)) * HD + c0 + ni * 8;
        *(float2*)(O + g0) = make_float2(acc[ni][0], acc[ni][1]);
        *(float2*)(O + g0 + 8 * HD) = make_float2(acc[ni][2], acc[ni][3]);
    }
}

extern "C" void kernel_launch(void* const* d_in, const int* in_sizes, int n_in,
                              void* d_out, int out_size) {
    const float* Q = (const float*)d_in[0];
    const float* K = (const float*)d_in[1];
    const float* V = (const float*)d_in[2];
    const int*   M = (const int*)  d_in[3];
    const float* P = (const float*)d_in[4];
    float* out = (float*)d_out;
    float* E   = out + OUT_ELEMS;

    cudaFuncSetAttribute(scores_k, cudaFuncAttributeMaxDynamicSharedMemorySize, S_SZ);
    cudaFuncSetAttribute(pv_k,     cudaFuncAttributeMaxDynamicSharedMemorySize, B_SZ);

    split_kv<<<KV_ELEMS / 4 / 256, 256>>>(K, V);
    scores_k<<<dim3(32, 16), 256, S_SZ>>>(Q, M, P, E);
    pv_k<<<dim3(32, 16), 256, B_SZ>>>(E, out);
}